// round 6
// baseline (speedup 1.0000x reference)
#include <cuda_runtime.h>
#include <cuda_bf16.h>
#include <cstdint>
#include <math.h>

// Problem constants
#define BATCH 4
#define H 1024
#define L 8192
#define KD 64
#define NS 4
#define TAPS 512

// Scratch
__device__ float g_filt[H * TAPS];                     // 2 MB
__device__ float g_v[(size_t)BATCH * H * L];           // 128 MB  v[b,f,l]

// ===========================================================================
// Helpers
// ===========================================================================
__device__ __forceinline__ uint32_t f2tf32(float x) {
    uint32_t r;
    asm("cvt.rna.tf32.f32 %0, %1;" : "=r"(r) : "f"(x));
    return r;
}
__device__ __forceinline__ uint32_t u2tf32(uint32_t x) {
    return f2tf32(__uint_as_float(x));
}

__device__ __forceinline__ void mma16n8k8(float d[4], const uint32_t a[4],
                                          const uint32_t b[2], const float c[4]) {
    asm volatile(
        "mma.sync.aligned.m16n8k8.row.col.f32.tf32.tf32.f32 "
        "{%0,%1,%2,%3}, {%4,%5,%6,%7}, {%8,%9}, {%10,%11,%12,%13};"
        : "=f"(d[0]), "=f"(d[1]), "=f"(d[2]), "=f"(d[3])
        : "r"(a[0]), "r"(a[1]), "r"(a[2]), "r"(a[3]),
          "r"(b[0]), "r"(b[1]),
          "f"(c[0]), "f"(c[1]), "f"(c[2]), "f"(c[3]));
}

__device__ __forceinline__ uint32_t smem_u32(const void* p) {
    uint32_t a;
    asm("{ .reg .u64 t; cvta.to.shared.u64 t, %1; cvt.u32.u64 %0, t; }" : "=r"(a) : "l"(p));
    return a;
}
__device__ __forceinline__ void cp_async16(uint32_t dst, const void* src) {
    asm volatile("cp.async.cg.shared.global [%0], [%1], 16;" :: "r"(dst), "l"(src));
}

// ===========================================================================
// Kernel 1: build the multi-resolution filter, L2-normalized per head.
// ===========================================================================
__global__ void build_filter_kernel(const float* __restrict__ k0,
                                    const float* __restrict__ k1,
                                    const float* __restrict__ k2,
                                    const float* __restrict__ k3) {
    int h = blockIdx.x;
    int t = threadIdx.x;

    const float* ks[NS] = {k0, k1, k2, k3};
    float acc = 0.0f;
#pragma unroll
    for (int i = 0; i < NS; ++i) {
        int len = KD << i;
        if (t < len) {
            float scale = (float)(1 << i);
            float coord = ((float)t + 0.5f) / scale - 0.5f;
            coord = fminf(fmaxf(coord, 0.0f), (float)(KD - 1));
            int lo = (int)floorf(coord);
            int hi = min(lo + 1, KD - 1);
            float w = coord - (float)lo;
            const float* kp = ks[i] + h * KD;
            float v = kp[lo] * (1.0f - w) + kp[hi] * w;
            acc += v * (float)(1 << (NS - 1 - i));
        }
    }

    __shared__ float red[TAPS];
    red[t] = acc * acc;
    __syncthreads();
#pragma unroll
    for (int s = TAPS / 2; s > 0; s >>= 1) {
        if (t < s) red[t] += red[t + s];
        __syncthreads();
    }
    float inv_norm = rsqrtf(red[0]);
    g_filt[h * TAPS + t] = acc * inv_norm;
}

// ===========================================================================
// Kernel 2: Toeplitz-MMA conv: y = k (*) u  + D*u, GeLU -> g_v
// ===========================================================================
#define UPAD_ROWS 136
#define UPAD_STRIDE 68

__global__ __launch_bounds__(128)
void conv_mma_kernel(const float* __restrict__ u, const float* __restrict__ D) {
    __shared__ uint32_t u_s[UPAD_ROWS * UPAD_STRIDE];
    __shared__ uint32_t k_s[640];

    int bh = blockIdx.x;
    int h  = bh & (H - 1);
    int tid  = threadIdx.x;
    int lane = tid & 31;
    int wid  = tid >> 5;
    int gid = lane >> 2;
    int tig = lane & 3;

    int wm0 = (wid & 1) * 64;
    int wn0 = (wid >> 1) * 32;

    const float* up = u + (size_t)bh * L;

    for (int i = tid; i < 640; i += 128) {
        int t = i - 64;
        float v = (t >= 0 && t < TAPS) ? g_filt[h * TAPS + t] : 0.0f;
        k_s[i] = f2tf32(v);
    }
    for (int j = tid; j < 512; j += 128)
        u_s[(j >> 6) * UPAD_STRIDE + (j & 63)] = 0u;
    for (int j = tid; j < L / 4; j += 128) {
        float4 x = ((const float4*)up)[j];
        int i = 512 + j * 4;
        uint32_t* p = u_s + (i >> 6) * UPAD_STRIDE + (i & 63);
        p[0] = f2tf32(x.x); p[1] = f2tf32(x.y);
        p[2] = f2tf32(x.z); p[3] = f2tf32(x.w);
    }
    __syncthreads();

    float acc[4][4][4];
#pragma unroll
    for (int s = 0; s < 4; ++s)
#pragma unroll
        for (int q = 0; q < 4; ++q)
#pragma unroll
            for (int e = 0; e < 4; ++e) acc[s][q][e] = 0.0f;

#pragma unroll 1
    for (int d = 0; d < 9; ++d) {
        int arow = (wm0 + gid + 8 - d) * UPAD_STRIDE + tig;
        int bb   = 64 + wn0 + gid - tig + 64 * d;
#pragma unroll
        for (int ms = 0; ms < 64; ms += 8) {
            uint32_t a[4][4];
#pragma unroll
            for (int s = 0; s < 4; ++s) {
                int base = arow + s * (16 * UPAD_STRIDE) + ms;
                a[s][0] = u_s[base];
                a[s][1] = u_s[base + 8 * UPAD_STRIDE];
                a[s][2] = u_s[base + 4];
                a[s][3] = u_s[base + 8 * UPAD_STRIDE + 4];
            }
            uint32_t bf[4][2];
#pragma unroll
            for (int q = 0; q < 4; ++q) {
                int kb = bb - ms + q * 8;
                bf[q][0] = k_s[kb];
                bf[q][1] = k_s[kb - 4];
            }
#pragma unroll
            for (int s = 0; s < 4; ++s)
#pragma unroll
                for (int q = 0; q < 4; ++q)
                    mma16n8k8(acc[s][q], a[s], bf[q], acc[s][q]);
        }
    }

    float dv = D[h];
    float* vp = g_v + (size_t)bh * L;
#pragma unroll
    for (int s = 0; s < 4; ++s) {
        int r0 = wm0 + s * 16 + gid;
#pragma unroll
        for (int q = 0; q < 4; ++q) {
            int n = wn0 + q * 8 + 2 * tig;
#pragma unroll
            for (int half = 0; half < 2; ++half) {
                int r = r0 + half * 8;
                float y0 = acc[s][q][half * 2 + 0];
                float y1 = acc[s][q][half * 2 + 1];
                float u0 = __uint_as_float(u_s[(r + 8) * UPAD_STRIDE + n]);
                float u1 = __uint_as_float(u_s[(r + 8) * UPAD_STRIDE + n + 1]);
                float x0 = y0 + dv * u0;
                float x1 = y1 + dv * u1;
                float g0 = 0.5f * x0 * (1.0f + erff(x0 * 0.70710678118654752f));
                float g1 = 0.5f * x1 * (1.0f + erff(x1 * 0.70710678118654752f));
                *(float2*)(vp + r * 64 + n) = make_float2(g0, g1);
            }
        }
    }
}

// ===========================================================================
// Kernel 3: tf32 mma.sync GEMM, cp.async 3-stage pipeline
//   out[b,o,l] = sum_f W[o,f] * v[b,f,l] + bias[o]
//   CTA tile 256(M=o) x 128(N=l) x BK=32; 8 warps (4M x 2N), warp 64x64.
// ===========================================================================
#define GBM 256
#define GBN 128
#define GBK 32
#define GAS 36            // A_s row stride (words)
#define GBS 136           // B_s row stride (words)
#define GSTG 3
#define A_STAGE_W (GBM * GAS)              // 9216 words
#define B_STAGE_W (GBK * GBS)              // 4352 words
#define STAGE_W (A_STAGE_W + B_STAGE_W)    // 13568 words
#define GEMM_SMEM_BYTES (GSTG * STAGE_W * 4)
#define GNCHUNK (H / GBK)                  // 32

extern __shared__ uint32_t g_smem[];

__global__ __launch_bounds__(256, 1)
void gemm_mma_pipe(const float* __restrict__ Wm,
                   const float* __restrict__ bias,
                   float* __restrict__ out) {
    int bz = blockIdx.z;
    int nb = blockIdx.x * GBN;
    int mb = blockIdx.y * GBM;
    const float* v = g_v + (size_t)bz * H * L;

    int tid  = threadIdx.x;
    int lane = tid & 31;
    int wid  = tid >> 5;
    int wm0 = (wid & 3) * 64;
    int wn0 = (wid >> 2) * 64;
    int gid = lane >> 2;
    int tig = lane & 3;

    uint32_t sbase = smem_u32(g_smem);

    // per-thread cp.async slots
    int a_row = tid >> 3, a_slot = tid & 7;       // +32 rows per rep (8 reps)
    int b_row = tid >> 5, b_slot = tid & 31;      // +8 rows per rep (4 reps)

    const float* Ag = Wm + (size_t)(mb + a_row) * H + a_slot * 4;
    const float* Bg = v + (size_t)b_row * L + nb + b_slot * 4;

    uint32_t a_doff = (uint32_t)(a_row * GAS + a_slot * 4) * 4u;
    uint32_t b_doff = (uint32_t)(b_row * GBS + b_slot * 4) * 4u;

#define ISSUE_CHUNK(c_) do {                                                  \
        int st_ = (c_) % GSTG;                                                \
        uint32_t sa_ = sbase + (uint32_t)(st_ * STAGE_W) * 4u;                \
        uint32_t sb_ = sa_ + (uint32_t)A_STAGE_W * 4u;                        \
        const float* ag_ = Ag + (c_) * GBK;                                   \
        const float* bg_ = Bg + (size_t)(c_) * GBK * L;                       \
        _Pragma("unroll")                                                     \
        for (int r_ = 0; r_ < 8; ++r_)                                        \
            cp_async16(sa_ + a_doff + (uint32_t)(r_ * 32 * GAS) * 4u,         \
                       ag_ + (size_t)(r_ * 32) * H);                          \
        _Pragma("unroll")                                                     \
        for (int r_ = 0; r_ < 4; ++r_)                                        \
            cp_async16(sb_ + b_doff + (uint32_t)(r_ * 8 * GBS) * 4u,          \
                       bg_ + (size_t)(r_ * 8) * L);                           \
    } while (0)

    // prologue: chunks 0..GSTG-2
#pragma unroll
    for (int c = 0; c < GSTG - 1; ++c) {
        ISSUE_CHUNK(c);
        asm volatile("cp.async.commit_group;" ::: "memory");
    }

    float acc[4][8][4];
#pragma unroll
    for (int s = 0; s < 4; ++s)
#pragma unroll
        for (int j = 0; j < 8; ++j)
#pragma unroll
            for (int e = 0; e < 4; ++e) acc[s][j][e] = 0.0f;

#pragma unroll 1
    for (int c = 0; c < GNCHUNK; ++c) {
        asm volatile("cp.async.wait_group %0;" :: "n"(GSTG - 2) : "memory");
        __syncthreads();

        // issue chunk c+GSTG-1 (overwrites stage consumed at iter c-1)
        if (c + GSTG - 1 < GNCHUNK) ISSUE_CHUNK(c + GSTG - 1);
        asm volatile("cp.async.commit_group;" ::: "memory");

        const uint32_t* As = g_smem + (c % GSTG) * STAGE_W;
        const uint32_t* Bs = As + A_STAGE_W;

#pragma unroll
        for (int kk = 0; kk < GBK; kk += 8) {
            uint32_t a[4][4];
#pragma unroll
            for (int s = 0; s < 4; ++s) {
                int m0 = wm0 + s * 16 + gid;
                a[s][0] = u2tf32(As[m0 * GAS + kk + tig]);
                a[s][1] = u2tf32(As[(m0 + 8) * GAS + kk + tig]);
                a[s][2] = u2tf32(As[m0 * GAS + kk + tig + 4]);
                a[s][3] = u2tf32(As[(m0 + 8) * GAS + kk + tig + 4]);
            }
            uint32_t bf[8][2];
#pragma unroll
            for (int j = 0; j < 8; ++j) {
                bf[j][0] = u2tf32(Bs[(kk + tig) * GBS + wn0 + j * 8 + gid]);
                bf[j][1] = u2tf32(Bs[(kk + tig + 4) * GBS + wn0 + j * 8 + gid]);
            }
#pragma unroll
            for (int s = 0; s < 4; ++s)
#pragma unroll
                for (int j = 0; j < 8; ++j)
                    mma16n8k8(acc[s][j], a[s], bf[j], acc[s][j]);
        }
    }

    // ---- epilogue ----
#pragma unroll
    for (int s = 0; s < 4; ++s) {
        int r0 = mb + wm0 + s * 16 + gid;
        int r1 = r0 + 8;
        float bv0 = bias[r0];
        float bv1 = bias[r1];
        float* o0 = out + ((size_t)bz * H + r0) * L + nb + wn0 + tig * 2;
        float* o1 = out + ((size_t)bz * H + r1) * L + nb + wn0 + tig * 2;
#pragma unroll
        for (int j = 0; j < 8; ++j) {
            *(float2*)(o0 + j * 8) = make_float2(acc[s][j][0] + bv0, acc[s][j][1] + bv0);
            *(float2*)(o1 + j * 8) = make_float2(acc[s][j][2] + bv1, acc[s][j][3] + bv1);
        }
    }
}

// ===========================================================================
// Launch
// ===========================================================================
extern "C" void kernel_launch(void* const* d_in, const int* in_sizes, int n_in,
                              void* d_out, int out_size) {
    const float* u  = (const float*)d_in[0];
    const float* k0 = (const float*)d_in[1];
    const float* k1 = (const float*)d_in[2];
    const float* k2 = (const float*)d_in[3];
    const float* k3 = (const float*)d_in[4];
    const float* D  = (const float*)d_in[5];
    const float* Wm = (const float*)d_in[6];
    const float* b  = (const float*)d_in[7];
    float* out = (float*)d_out;

    build_filter_kernel<<<H, TAPS>>>(k0, k1, k2, k3);

    conv_mma_kernel<<<BATCH * H, 128>>>(u, D);

    static bool attr_set = false;
    if (!attr_set) {
        cudaFuncSetAttribute(gemm_mma_pipe,
                             cudaFuncAttributeMaxDynamicSharedMemorySize,
                             GEMM_SMEM_BYTES);
        attr_set = true;
    }
    dim3 ggrid(L / GBN, H / GBM, BATCH);
    gemm_mma_pipe<<<ggrid, 256, GEMM_SMEM_BYTES>>>(Wm, b, out);
}

// round 7
// speedup vs baseline: 1.6249x; 1.6249x over previous
#include <cuda_runtime.h>
#include <cuda_bf16.h>
#include <cstdint>
#include <math.h>

// Problem constants
#define BATCH 4
#define H 1024
#define L 8192
#define KD 64
#define NS 4
#define TAPS 512

// Scratch
__device__ float g_filt[H * TAPS];                     // 2 MB
__device__ float g_v[(size_t)BATCH * H * L];           // 128 MB  v[b,f,l] (tf32-valued)
__device__ float g_w32[H * H];                         // 4 MB    W (tf32-valued)

// ===========================================================================
// Helpers
// ===========================================================================
__device__ __forceinline__ uint32_t f2tf32(float x) {
    uint32_t r;
    asm("cvt.rna.tf32.f32 %0, %1;" : "=r"(r) : "f"(x));
    return r;
}

__device__ __forceinline__ void mma16n8k8(float d[4], const uint32_t a[4],
                                          const uint32_t b[2], const float c[4]) {
    asm volatile(
        "mma.sync.aligned.m16n8k8.row.col.f32.tf32.tf32.f32 "
        "{%0,%1,%2,%3}, {%4,%5,%6,%7}, {%8,%9}, {%10,%11,%12,%13};"
        : "=f"(d[0]), "=f"(d[1]), "=f"(d[2]), "=f"(d[3])
        : "r"(a[0]), "r"(a[1]), "r"(a[2]), "r"(a[3]),
          "r"(b[0]), "r"(b[1]),
          "f"(c[0]), "f"(c[1]), "f"(c[2]), "f"(c[3]));
}

__device__ __forceinline__ uint32_t smem_u32(const void* p) {
    uint32_t a;
    asm("{ .reg .u64 t; cvta.to.shared.u64 t, %1; cvt.u32.u64 %0, t; }" : "=r"(a) : "l"(p));
    return a;
}
__device__ __forceinline__ void cp_async16(uint32_t dst, const void* src) {
    asm volatile("cp.async.cg.shared.global [%0], [%1], 16;" :: "r"(dst), "l"(src));
}

// ===========================================================================
// Kernel 1: build the multi-resolution filter, L2-normalized per head.
// ===========================================================================
__global__ void build_filter_kernel(const float* __restrict__ k0,
                                    const float* __restrict__ k1,
                                    const float* __restrict__ k2,
                                    const float* __restrict__ k3) {
    int h = blockIdx.x;
    int t = threadIdx.x;

    const float* ks[NS] = {k0, k1, k2, k3};
    float acc = 0.0f;
#pragma unroll
    for (int i = 0; i < NS; ++i) {
        int len = KD << i;
        if (t < len) {
            float scale = (float)(1 << i);
            float coord = ((float)t + 0.5f) / scale - 0.5f;
            coord = fminf(fmaxf(coord, 0.0f), (float)(KD - 1));
            int lo = (int)floorf(coord);
            int hi = min(lo + 1, KD - 1);
            float w = coord - (float)lo;
            const float* kp = ks[i] + h * KD;
            float v = kp[lo] * (1.0f - w) + kp[hi] * w;
            acc += v * (float)(1 << (NS - 1 - i));
        }
    }

    __shared__ float red[TAPS];
    red[t] = acc * acc;
    __syncthreads();
#pragma unroll
    for (int s = TAPS / 2; s > 0; s >>= 1) {
        if (t < s) red[t] += red[t + s];
        __syncthreads();
    }
    float inv_norm = rsqrtf(red[0]);
    g_filt[h * TAPS + t] = acc * inv_norm;
}

// ===========================================================================
// Kernel 1b: W -> tf32-valued copy
// ===========================================================================
__global__ void wprep_kernel(const float* __restrict__ Wm) {
    int i = blockIdx.x * 256 + threadIdx.x;
    g_w32[i] = __uint_as_float(f2tf32(Wm[i]));
}

// ===========================================================================
// Kernel 2: Toeplitz-MMA conv: y = k (*) u  + D*u, GeLU -> g_v (tf32-valued)
// ===========================================================================
#define UPAD_ROWS 136
#define UPAD_STRIDE 68

__global__ __launch_bounds__(128)
void conv_mma_kernel(const float* __restrict__ u, const float* __restrict__ D) {
    __shared__ uint32_t u_s[UPAD_ROWS * UPAD_STRIDE];
    __shared__ uint32_t k_s[640];

    int bh = blockIdx.x;
    int h  = bh & (H - 1);
    int tid  = threadIdx.x;
    int lane = tid & 31;
    int wid  = tid >> 5;
    int gid = lane >> 2;
    int tig = lane & 3;

    int wm0 = (wid & 1) * 64;
    int wn0 = (wid >> 1) * 32;

    const float* up = u + (size_t)bh * L;

    for (int i = tid; i < 640; i += 128) {
        int t = i - 64;
        float v = (t >= 0 && t < TAPS) ? g_filt[h * TAPS + t] : 0.0f;
        k_s[i] = f2tf32(v);
    }
    for (int j = tid; j < 512; j += 128)
        u_s[(j >> 6) * UPAD_STRIDE + (j & 63)] = 0u;
    for (int j = tid; j < L / 4; j += 128) {
        float4 x = ((const float4*)up)[j];
        int i = 512 + j * 4;
        uint32_t* p = u_s + (i >> 6) * UPAD_STRIDE + (i & 63);
        p[0] = f2tf32(x.x); p[1] = f2tf32(x.y);
        p[2] = f2tf32(x.z); p[3] = f2tf32(x.w);
    }
    __syncthreads();

    float acc[4][4][4];
#pragma unroll
    for (int s = 0; s < 4; ++s)
#pragma unroll
        for (int q = 0; q < 4; ++q)
#pragma unroll
            for (int e = 0; e < 4; ++e) acc[s][q][e] = 0.0f;

#pragma unroll 1
    for (int d = 0; d < 9; ++d) {
        int arow = (wm0 + gid + 8 - d) * UPAD_STRIDE + tig;
        int bb   = 64 + wn0 + gid - tig + 64 * d;
#pragma unroll
        for (int ms = 0; ms < 64; ms += 8) {
            uint32_t a[4][4];
#pragma unroll
            for (int s = 0; s < 4; ++s) {
                int base = arow + s * (16 * UPAD_STRIDE) + ms;
                a[s][0] = u_s[base];
                a[s][1] = u_s[base + 8 * UPAD_STRIDE];
                a[s][2] = u_s[base + 4];
                a[s][3] = u_s[base + 8 * UPAD_STRIDE + 4];
            }
            uint32_t bf[4][2];
#pragma unroll
            for (int q = 0; q < 4; ++q) {
                int kb = bb - ms + q * 8;
                bf[q][0] = k_s[kb];
                bf[q][1] = k_s[kb - 4];
            }
#pragma unroll
            for (int s = 0; s < 4; ++s)
#pragma unroll
                for (int q = 0; q < 4; ++q)
                    mma16n8k8(acc[s][q], a[s], bf[q], acc[s][q]);
        }
    }

    float dv = D[h];
    float* vp = g_v + (size_t)bh * L;
#pragma unroll
    for (int s = 0; s < 4; ++s) {
        int r0 = wm0 + s * 16 + gid;
#pragma unroll
        for (int q = 0; q < 4; ++q) {
            int n = wn0 + q * 8 + 2 * tig;
#pragma unroll
            for (int half = 0; half < 2; ++half) {
                int r = r0 + half * 8;
                float y0 = acc[s][q][half * 2 + 0];
                float y1 = acc[s][q][half * 2 + 1];
                float u0 = __uint_as_float(u_s[(r + 8) * UPAD_STRIDE + n]);
                float u1 = __uint_as_float(u_s[(r + 8) * UPAD_STRIDE + n + 1]);
                float x0 = y0 + dv * u0;
                float x1 = y1 + dv * u1;
                float g0 = 0.5f * x0 * (1.0f + erff(x0 * 0.70710678118654752f));
                float g1 = 0.5f * x1 * (1.0f + erff(x1 * 0.70710678118654752f));
                // store tf32-VALUED floats: GEMM consumes raw bits, no cvt
                *(float2*)(vp + r * 64 + n) =
                    make_float2(__uint_as_float(f2tf32(g0)), __uint_as_float(f2tf32(g1)));
            }
        }
    }
}

// ===========================================================================
// Kernel 3: tf32 mma.sync GEMM, cp.async 3-stage pipeline, no in-loop cvt.
//   out[b,o,l] = sum_f W[o,f] * v[b,f,l] + bias[o]
//   CTA tile 256(M=o) x 128(N=l) x BK=32; 8 warps (4M x 2N), warp 64x64.
// ===========================================================================
#define GBM 256
#define GBN 128
#define GBK 32
#define GAS 36            // A_s row stride (words)
#define GBS 136           // B_s row stride (words)
#define GSTG 3
#define A_STAGE_W (GBM * GAS)              // 9216 words
#define B_STAGE_W (GBK * GBS)              // 4352 words
#define STAGE_W (A_STAGE_W + B_STAGE_W)    // 13568 words
#define GEMM_SMEM_BYTES (GSTG * STAGE_W * 4)
#define GNCHUNK (H / GBK)                  // 32

extern __shared__ uint32_t g_smem[];

__global__ __launch_bounds__(256, 1)
void gemm_mma_pipe(const float* __restrict__ bias, float* __restrict__ out) {
    int bz = blockIdx.z;
    int nb = blockIdx.x * GBN;
    int mb = blockIdx.y * GBM;
    const float* v = g_v + (size_t)bz * H * L;

    int tid  = threadIdx.x;
    int lane = tid & 31;
    int wid  = tid >> 5;
    int wm0 = (wid & 3) * 64;
    int wn0 = (wid >> 2) * 64;
    int gid = lane >> 2;
    int tig = lane & 3;

    uint32_t sbase = smem_u32(g_smem);

    int a_row = tid >> 3, a_slot = tid & 7;
    int b_row = tid >> 5, b_slot = tid & 31;

    const float* Ag = g_w32 + (size_t)(mb + a_row) * H + a_slot * 4;
    const float* Bg = v + (size_t)b_row * L + nb + b_slot * 4;

    uint32_t a_doff = (uint32_t)(a_row * GAS + a_slot * 4) * 4u;
    uint32_t b_doff = (uint32_t)(b_row * GBS + b_slot * 4) * 4u;

#define ISSUE_CHUNK(c_) do {                                                  \
        int st_ = (c_) % GSTG;                                                \
        uint32_t sa_ = sbase + (uint32_t)(st_ * STAGE_W) * 4u;                \
        uint32_t sb_ = sa_ + (uint32_t)A_STAGE_W * 4u;                        \
        const float* ag_ = Ag + (c_) * GBK;                                   \
        const float* bg_ = Bg + (size_t)(c_) * GBK * L;                       \
        _Pragma("unroll")                                                     \
        for (int r_ = 0; r_ < 8; ++r_)                                        \
            cp_async16(sa_ + a_doff + (uint32_t)(r_ * 32 * GAS) * 4u,         \
                       ag_ + (size_t)(r_ * 32) * H);                          \
        _Pragma("unroll")                                                     \
        for (int r_ = 0; r_ < 4; ++r_)                                        \
            cp_async16(sb_ + b_doff + (uint32_t)(r_ * 8 * GBS) * 4u,          \
                       bg_ + (size_t)(r_ * 8) * L);                           \
    } while (0)

#pragma unroll
    for (int c = 0; c < GSTG - 1; ++c) {
        ISSUE_CHUNK(c);
        asm volatile("cp.async.commit_group;" ::: "memory");
    }

    float acc[4][8][4];
#pragma unroll
    for (int s = 0; s < 4; ++s)
#pragma unroll
        for (int j = 0; j < 8; ++j)
#pragma unroll
            for (int e = 0; e < 4; ++e) acc[s][j][e] = 0.0f;

#pragma unroll 1
    for (int c = 0; c < GNCHUNK; ++c) {
        asm volatile("cp.async.wait_group %0;" :: "n"(GSTG - 2) : "memory");
        __syncthreads();

        if (c + GSTG - 1 < GNCHUNK) ISSUE_CHUNK(c + GSTG - 1);
        asm volatile("cp.async.commit_group;" ::: "memory");

        const uint32_t* As = g_smem + (c % GSTG) * STAGE_W;
        const uint32_t* Bs = As + A_STAGE_W;

#pragma unroll
        for (int kk = 0; kk < GBK; kk += 8) {
            uint32_t a[4][4];
#pragma unroll
            for (int s = 0; s < 4; ++s) {
                int m0 = wm0 + s * 16 + gid;
                a[s][0] = As[m0 * GAS + kk + tig];
                a[s][1] = As[(m0 + 8) * GAS + kk + tig];
                a[s][2] = As[m0 * GAS + kk + tig + 4];
                a[s][3] = As[(m0 + 8) * GAS + kk + tig + 4];
            }
            uint32_t bf[8][2];
#pragma unroll
            for (int j = 0; j < 8; ++j) {
                bf[j][0] = Bs[(kk + tig) * GBS + wn0 + j * 8 + gid];
                bf[j][1] = Bs[(kk + tig + 4) * GBS + wn0 + j * 8 + gid];
            }
#pragma unroll
            for (int s = 0; s < 4; ++s)
#pragma unroll
                for (int j = 0; j < 8; ++j)
                    mma16n8k8(acc[s][j], a[s], bf[j], acc[s][j]);
        }
    }

    // ---- epilogue ----
#pragma unroll
    for (int s = 0; s < 4; ++s) {
        int r0 = mb + wm0 + s * 16 + gid;
        int r1 = r0 + 8;
        float bv0 = bias[r0];
        float bv1 = bias[r1];
        float* o0 = out + ((size_t)bz * H + r0) * L + nb + wn0 + tig * 2;
        float* o1 = out + ((size_t)bz * H + r1) * L + nb + wn0 + tig * 2;
#pragma unroll
        for (int j = 0; j < 8; ++j) {
            *(float2*)(o0 + j * 8) = make_float2(acc[s][j][0] + bv0, acc[s][j][1] + bv0);
            *(float2*)(o1 + j * 8) = make_float2(acc[s][j][2] + bv1, acc[s][j][3] + bv1);
        }
    }
}

// ===========================================================================
// Launch
// ===========================================================================
extern "C" void kernel_launch(void* const* d_in, const int* in_sizes, int n_in,
                              void* d_out, int out_size) {
    const float* u  = (const float*)d_in[0];
    const float* k0 = (const float*)d_in[1];
    const float* k1 = (const float*)d_in[2];
    const float* k2 = (const float*)d_in[3];
    const float* k3 = (const float*)d_in[4];
    const float* D  = (const float*)d_in[5];
    const float* Wm = (const float*)d_in[6];
    const float* b  = (const float*)d_in[7];
    float* out = (float*)d_out;

    build_filter_kernel<<<H, TAPS>>>(k0, k1, k2, k3);
    wprep_kernel<<<H * H / 256, 256>>>(Wm);

    conv_mma_kernel<<<BATCH * H, 128>>>(u, D);

    static bool attr_set = false;
    if (!attr_set) {
        cudaFuncSetAttribute(gemm_mma_pipe,
                             cudaFuncAttributeMaxDynamicSharedMemorySize,
                             GEMM_SMEM_BYTES);
        attr_set = true;
    }
    dim3 ggrid(L / GBN, H / GBM, BATCH);
    gemm_mma_pipe<<<ggrid, 256, GEMM_SMEM_BYTES>>>(b, out);
}